// round 1
// baseline (speedup 1.0000x reference)
#include <cuda_runtime.h>
#include <cuda_bf16.h>

// Problem constants
#define BB 8
#define LL 2048
#define DD 512
#define RR 512
#define M1 (BB * LL)   // 16384 flattened (B,L)

// ---------------- scratch (device globals: no allocation allowed) ----------
__device__ float g_q[(size_t)M1 * DD];       // q projection   (B*L, D)
__device__ float g_z[(size_t)M1 * RR];       // logits -> Fss  (B*L, R)
__device__ float g_invw2[RR * DD];           // 1/w^2
__device__ float g_b2[RR * DD];              // -2*c/w^2
__device__ float g_cc[RR];                   // sum c^2/w^2
__device__ float g_conq[BB * RR * DD];       // (B, R, D)

// ---------------- tiling ----------------
#define BM 128
#define BN 64
#define BK 16
#define NT 256

// ---------------------------------------------------------------------------
// prep: inv_w2, b2 = -2*c*inv_w2, cc[r] = sum_d c^2*inv_w2
// ---------------------------------------------------------------------------
__global__ void prep_kernel(const float* __restrict__ centers,
                            const float* __restrict__ widths) {
    int r = blockIdx.x;
    int t = threadIdx.x;  // 128
    float acc = 0.f;
    for (int d = t; d < DD; d += 128) {
        float w = widths[r * DD + d];
        float c = centers[r * DD + d];
        float iw = 1.0f / (w * w);
        g_invw2[r * DD + d] = iw;
        g_b2[r * DD + d] = -2.0f * c * iw;
        acc += c * c * iw;
    }
    __shared__ float sred[128];
    sred[t] = acc;
    __syncthreads();
    for (int s = 64; s > 0; s >>= 1) {
        if (t < s) sred[t] += sred[t + s];
        __syncthreads();
    }
    if (t == 0) g_cc[r] = sred[0];
}

// ---------------------------------------------------------------------------
// K1: q = query @ Wq^T + bq   (NT gemm, M1 x DD, K = DD) -> g_q
// ---------------------------------------------------------------------------
__global__ __launch_bounds__(NT) void k1_qproj(const float* __restrict__ A,
                                               const float* __restrict__ Wq,
                                               const float* __restrict__ bq) {
    __shared__ float As[BK][BM];
    __shared__ float Bs[BK][BN];
    const int K = DD, N = DD;
    int t = threadIdx.x;
    int bm = blockIdx.x * BM;
    int bn = blockIdx.y * BN;
    int tx = t & 15, ty = t >> 4;
    float acc[8][4] = {};
    for (int k0 = 0; k0 < K; k0 += BK) {
#pragma unroll
        for (int i = 0; i < 2; i++) {
            int idx = t + i * NT;            // 0..511
            int row = idx >> 2;
            int k4 = (idx & 3) * 4;
            float4 v = *(const float4*)(A + (size_t)(bm + row) * K + k0 + k4);
            As[k4 + 0][row] = v.x; As[k4 + 1][row] = v.y;
            As[k4 + 2][row] = v.z; As[k4 + 3][row] = v.w;
        }
        {
            int row = t >> 2;
            int k4 = (t & 3) * 4;
            float4 v = *(const float4*)(Wq + (size_t)(bn + row) * K + k0 + k4);
            Bs[k4 + 0][row] = v.x; Bs[k4 + 1][row] = v.y;
            Bs[k4 + 2][row] = v.z; Bs[k4 + 3][row] = v.w;
        }
        __syncthreads();
#pragma unroll
        for (int k = 0; k < BK; k++) {
            float a[8], b[4];
#pragma unroll
            for (int i = 0; i < 8; i++) a[i] = As[k][ty * 8 + i];
#pragma unroll
            for (int j = 0; j < 4; j++) b[j] = Bs[k][tx * 4 + j];
#pragma unroll
            for (int i = 0; i < 8; i++)
#pragma unroll
                for (int j = 0; j < 4; j++) acc[i][j] += a[i] * b[j];
        }
        __syncthreads();
    }
#pragma unroll
    for (int i = 0; i < 8; i++) {
        int row = bm + ty * 8 + i;
#pragma unroll
        for (int j = 0; j < 4; j++) {
            int col = bn + tx * 4 + j;
            g_q[(size_t)row * N + col] = acc[i][j] + bq[col];
        }
    }
}

// ---------------------------------------------------------------------------
// K2: z_pre[m,r] = sum_d q*(q*invw2 + b2)  (dual-B NT gemm) -> g_z
// ---------------------------------------------------------------------------
__global__ __launch_bounds__(NT) void k2_logits() {
    __shared__ float As[BK][BM];
    __shared__ float B1s[BK][BN];
    __shared__ float B2s[BK][BN];
    const int K = DD, N = RR;
    int t = threadIdx.x;
    int bm = blockIdx.x * BM;
    int bn = blockIdx.y * BN;
    int tx = t & 15, ty = t >> 4;
    float acc[8][4] = {};
    for (int k0 = 0; k0 < K; k0 += BK) {
#pragma unroll
        for (int i = 0; i < 2; i++) {
            int idx = t + i * NT;
            int row = idx >> 2;
            int k4 = (idx & 3) * 4;
            float4 v = *(const float4*)(g_q + (size_t)(bm + row) * K + k0 + k4);
            As[k4 + 0][row] = v.x; As[k4 + 1][row] = v.y;
            As[k4 + 2][row] = v.z; As[k4 + 3][row] = v.w;
        }
        {
            int row = t >> 2;
            int k4 = (t & 3) * 4;
            float4 v1 = *(const float4*)(g_invw2 + (size_t)(bn + row) * K + k0 + k4);
            B1s[k4 + 0][row] = v1.x; B1s[k4 + 1][row] = v1.y;
            B1s[k4 + 2][row] = v1.z; B1s[k4 + 3][row] = v1.w;
            float4 v2 = *(const float4*)(g_b2 + (size_t)(bn + row) * K + k0 + k4);
            B2s[k4 + 0][row] = v2.x; B2s[k4 + 1][row] = v2.y;
            B2s[k4 + 2][row] = v2.z; B2s[k4 + 3][row] = v2.w;
        }
        __syncthreads();
#pragma unroll
        for (int k = 0; k < BK; k++) {
            float a[8], b1[4], b2[4];
#pragma unroll
            for (int i = 0; i < 8; i++) a[i] = As[k][ty * 8 + i];
#pragma unroll
            for (int j = 0; j < 4; j++) { b1[j] = B1s[k][tx * 4 + j]; b2[j] = B2s[k][tx * 4 + j]; }
#pragma unroll
            for (int i = 0; i < 8; i++)
#pragma unroll
                for (int j = 0; j < 4; j++) {
                    float tt = a[i] * b1[j] + b2[j];
                    acc[i][j] += a[i] * tt;
                }
        }
        __syncthreads();
    }
#pragma unroll
    for (int i = 0; i < 8; i++) {
        int row = bm + ty * 8 + i;
#pragma unroll
        for (int j = 0; j < 4; j++) {
            int col = bn + tx * 4 + j;
            g_z[(size_t)row * N + col] = acc[i][j];
        }
    }
}

// ---------------------------------------------------------------------------
// K3: softmax over R (in place on g_z):  v = -(0.5/D)*(z_pre + cc[r])
// ---------------------------------------------------------------------------
__global__ void softmax_kernel() {
    int row = blockIdx.x;
    int t = threadIdx.x;  // 256
    const float scale = -0.5f / (float)DD;
    float* zrow = g_z + (size_t)row * RR;
    float v0 = scale * (zrow[t] + g_cc[t]);
    float v1 = scale * (zrow[t + 256] + g_cc[t + 256]);
    float m = fmaxf(v0, v1);
#pragma unroll
    for (int o = 16; o > 0; o >>= 1) m = fmaxf(m, __shfl_xor_sync(0xffffffffu, m, o));
    __shared__ float sm[8];
    __shared__ float ss[8];
    int wid = t >> 5, lid = t & 31;
    if (lid == 0) sm[wid] = m;
    __syncthreads();
    float mm = sm[0];
#pragma unroll
    for (int i = 1; i < 8; i++) mm = fmaxf(mm, sm[i]);
    float e0 = __expf(v0 - mm), e1 = __expf(v1 - mm);
    float s = e0 + e1;
#pragma unroll
    for (int o = 16; o > 0; o >>= 1) s += __shfl_xor_sync(0xffffffffu, s, o);
    if (lid == 0) ss[wid] = s;
    __syncthreads();
    float tot = 0.f;
#pragma unroll
    for (int i = 0; i < 8; i++) tot += ss[i];
    float inv = 1.0f / tot;
    zrow[t] = e0 * inv;
    zrow[t + 256] = e1 * inv;
}

// ---------------------------------------------------------------------------
// K4: conq[b,r,d] = sum_l Wc[r,l] * query[b,l,d] + bc[r]   (NN gemm per batch)
//     M = RR, N = DD, K = LL
// ---------------------------------------------------------------------------
__global__ __launch_bounds__(NT) void k4_conq(const float* __restrict__ Wc,
                                              const float* __restrict__ query,
                                              const float* __restrict__ bc) {
    __shared__ float As[BK][BM];
    __shared__ float Bs[BK][BN];
    const int K = LL, N = DD;
    int b = blockIdx.z;
    const float* Bm = query + (size_t)b * LL * DD;
    float* C = g_conq + (size_t)b * RR * DD;
    int t = threadIdx.x;
    int bm = blockIdx.x * BM;
    int bn = blockIdx.y * BN;
    int tx = t & 15, ty = t >> 4;
    float acc[8][4] = {};
    for (int k0 = 0; k0 < K; k0 += BK) {
#pragma unroll
        for (int i = 0; i < 2; i++) {
            int idx = t + i * NT;
            int row = idx >> 2;
            int k4 = (idx & 3) * 4;
            float4 v = *(const float4*)(Wc + (size_t)(bm + row) * K + k0 + k4);
            As[k4 + 0][row] = v.x; As[k4 + 1][row] = v.y;
            As[k4 + 2][row] = v.z; As[k4 + 3][row] = v.w;
        }
        {
            int krow = t >> 4;
            int n4 = (t & 15) * 4;
            float4 v = *(const float4*)(Bm + (size_t)(k0 + krow) * N + bn + n4);
            *(float4*)&Bs[krow][n4] = v;
        }
        __syncthreads();
#pragma unroll
        for (int k = 0; k < BK; k++) {
            float a[8], bfr[4];
#pragma unroll
            for (int i = 0; i < 8; i++) a[i] = As[k][ty * 8 + i];
#pragma unroll
            for (int j = 0; j < 4; j++) bfr[j] = Bs[k][tx * 4 + j];
#pragma unroll
            for (int i = 0; i < 8; i++)
#pragma unroll
                for (int j = 0; j < 4; j++) acc[i][j] += a[i] * bfr[j];
        }
        __syncthreads();
    }
#pragma unroll
    for (int i = 0; i < 8; i++) {
        int row = bm + ty * 8 + i;
        float bias = bc[row];
#pragma unroll
        for (int j = 0; j < 4; j++) {
            int col = bn + tx * 4 + j;
            C[(size_t)row * N + col] = acc[i][j] + bias;
        }
    }
}

// ---------------------------------------------------------------------------
// K5: out[b,l,d] = sum_r Fss[b,l,r] * conq[b,r,d]    (NN gemm per batch)
//     M = LL, N = DD, K = RR
// ---------------------------------------------------------------------------
__global__ __launch_bounds__(NT) void k5_apply(float* __restrict__ out) {
    __shared__ float As[BK][BM];
    __shared__ float Bs[BK][BN];
    const int K = RR, N = DD;
    int b = blockIdx.z;
    const float* A = g_z + (size_t)b * LL * RR;
    const float* Bm = g_conq + (size_t)b * RR * DD;
    float* C = out + (size_t)b * LL * DD;
    int t = threadIdx.x;
    int bm = blockIdx.x * BM;
    int bn = blockIdx.y * BN;
    int tx = t & 15, ty = t >> 4;
    float acc[8][4] = {};
    for (int k0 = 0; k0 < K; k0 += BK) {
#pragma unroll
        for (int i = 0; i < 2; i++) {
            int idx = t + i * NT;
            int row = idx >> 2;
            int k4 = (idx & 3) * 4;
            float4 v = *(const float4*)(A + (size_t)(bm + row) * K + k0 + k4);
            As[k4 + 0][row] = v.x; As[k4 + 1][row] = v.y;
            As[k4 + 2][row] = v.z; As[k4 + 3][row] = v.w;
        }
        {
            int krow = t >> 4;
            int n4 = (t & 15) * 4;
            float4 v = *(const float4*)(Bm + (size_t)(k0 + krow) * N + bn + n4);
            *(float4*)&Bs[krow][n4] = v;
        }
        __syncthreads();
#pragma unroll
        for (int k = 0; k < BK; k++) {
            float a[8], bfr[4];
#pragma unroll
            for (int i = 0; i < 8; i++) a[i] = As[k][ty * 8 + i];
#pragma unroll
            for (int j = 0; j < 4; j++) bfr[j] = Bs[k][tx * 4 + j];
#pragma unroll
            for (int i = 0; i < 8; i++)
#pragma unroll
                for (int j = 0; j < 4; j++) acc[i][j] += a[i] * bfr[j];
        }
        __syncthreads();
    }
#pragma unroll
    for (int i = 0; i < 8; i++) {
        int row = bm + ty * 8 + i;
#pragma unroll
        for (int j = 0; j < 4; j++) {
            int col = bn + tx * 4 + j;
            C[(size_t)row * N + col] = acc[i][j];
        }
    }
}

// ---------------------------------------------------------------------------
extern "C" void kernel_launch(void* const* d_in, const int* in_sizes, int n_in,
                              void* d_out, int out_size) {
    const float* query   = (const float*)d_in[0];   // (B,L,D)
    const float* Wq      = (const float*)d_in[1];   // (D,D)
    const float* bq      = (const float*)d_in[2];   // (D,)
    const float* Wc      = (const float*)d_in[3];   // (R,L)
    const float* bc      = (const float*)d_in[4];   // (R,)
    const float* centers = (const float*)d_in[5];   // (R,D)
    const float* widths  = (const float*)d_in[6];   // (R,D)
    float* out = (float*)d_out;                     // (B,L,D)

    prep_kernel<<<RR, 128>>>(centers, widths);

    dim3 g1(M1 / BM, DD / BN);
    k1_qproj<<<g1, NT>>>(query, Wq, bq);

    dim3 g2(M1 / BM, RR / BN);
    k2_logits<<<g2, NT>>>();

    softmax_kernel<<<M1, 256>>>();

    dim3 g4(RR / BM, DD / BN, BB);
    k4_conq<<<g4, NT>>>(Wc, query, bc);

    dim3 g5(LL / BM, DD / BN, BB);
    k5_apply<<<g5, NT>>>(out);
}

// round 2
// speedup vs baseline: 1.6627x; 1.6627x over previous
#include <cuda_runtime.h>
#include <cuda_bf16.h>

// Problem constants
#define BB 8
#define LL 2048
#define DD 512
#define RR 512
#define M1 (BB * LL)   // 16384 flattened (B,L)

// ---------------- scratch (device globals: no allocation allowed) ----------
__device__ float g_q[(size_t)M1 * DD];       // q projection   (B*L, D)
__device__ float g_z[(size_t)M1 * RR];       // logits -> Fss  (B*L, R)
__device__ float g_invw2[RR * DD];           // 1/w^2
__device__ float g_b2[RR * DD];              // -2*c/w^2
__device__ float g_cc[RR];                   // sum c^2/w^2
__device__ float g_conq[BB * RR * DD];       // (B, R, D)

// ---------------- tiling ----------------
#define BM 128
#define BN 128
#define BK 8
#define NT 256
#define BMP 132   // padded row stride (floats); 132*4B = 528B, 16B-aligned

#define ST4(arr, kq, idx, v)               \
    arr[(kq) + 0][idx] = (v).x;            \
    arr[(kq) + 1][idx] = (v).y;            \
    arr[(kq) + 2][idx] = (v).z;            \
    arr[(kq) + 3][idx] = (v).w;

// ---------------------------------------------------------------------------
// prep: inv_w2, b2 = -2*c*inv_w2, cc[r] = sum_d c^2*inv_w2
// ---------------------------------------------------------------------------
__global__ void prep_kernel(const float* __restrict__ centers,
                            const float* __restrict__ widths) {
    int r = blockIdx.x;
    int t = threadIdx.x;  // 128
    float acc = 0.f;
    for (int d = t; d < DD; d += 128) {
        float w = widths[r * DD + d];
        float c = centers[r * DD + d];
        float iw = 1.0f / (w * w);
        g_invw2[r * DD + d] = iw;
        g_b2[r * DD + d] = -2.0f * c * iw;
        acc += c * c * iw;
    }
    __shared__ float sred[128];
    sred[t] = acc;
    __syncthreads();
    for (int s = 64; s > 0; s >>= 1) {
        if (t < s) sred[t] += sred[t + s];
        __syncthreads();
    }
    if (t == 0) g_cc[r] = sred[0];
}

// ---------------------------------------------------------------------------
// K1: q = query @ Wq^T + bq   (NT gemm: A (M,K) rowmaj, B (N,K) rowmaj)
// ---------------------------------------------------------------------------
__global__ __launch_bounds__(NT, 2) void k1_qproj(const float* __restrict__ A,
                                                  const float* __restrict__ Wq,
                                                  const float* __restrict__ bq) {
    __shared__ float As[2][BK][BMP];
    __shared__ float Bs[2][BK][BMP];
    const int K = DD, N = DD;
    int t = threadIdx.x;
    int bm = blockIdx.x * BM;
    int bn = blockIdx.y * BN;
    int tx = t & 15, ty = t >> 4;
    int lr = t >> 1;           // 0..127
    int lk = (t & 1) * 4;      // 0 or 4
    const float* Ap = A + (size_t)(bm + lr) * K + lk;
    const float* Bp = Wq + (size_t)(bn + lr) * K + lk;
    float acc[8][8] = {};
    {
        float4 va = *(const float4*)Ap;
        float4 vb = *(const float4*)Bp;
        ST4(As[0], lk, lr, va);
        ST4(Bs[0], lk, lr, vb);
    }
    __syncthreads();
    const int nk = K / BK;
    float4 pa, pb;
    for (int kt = 0; kt < nk; kt++) {
        int buf = kt & 1;
        if (kt + 1 < nk) {
            pa = *(const float4*)(Ap + (kt + 1) * BK);
            pb = *(const float4*)(Bp + (kt + 1) * BK);
        }
#pragma unroll
        for (int k = 0; k < BK; k++) {
            float4 a0 = *(const float4*)&As[buf][k][ty * 8];
            float4 a1 = *(const float4*)&As[buf][k][ty * 8 + 4];
            float4 b0 = *(const float4*)&Bs[buf][k][tx * 8];
            float4 b1 = *(const float4*)&Bs[buf][k][tx * 8 + 4];
            float a[8] = {a0.x, a0.y, a0.z, a0.w, a1.x, a1.y, a1.z, a1.w};
            float b[8] = {b0.x, b0.y, b0.z, b0.w, b1.x, b1.y, b1.z, b1.w};
#pragma unroll
            for (int i = 0; i < 8; i++)
#pragma unroll
                for (int j = 0; j < 8; j++) acc[i][j] += a[i] * b[j];
        }
        if (kt + 1 < nk) {
            ST4(As[buf ^ 1], lk, lr, pa);
            ST4(Bs[buf ^ 1], lk, lr, pb);
        }
        __syncthreads();
    }
    float4 bv0 = *(const float4*)(bq + bn + tx * 8);
    float4 bv1 = *(const float4*)(bq + bn + tx * 8 + 4);
#pragma unroll
    for (int i = 0; i < 8; i++) {
        int row = bm + ty * 8 + i;
        float4 o0 = {acc[i][0] + bv0.x, acc[i][1] + bv0.y,
                     acc[i][2] + bv0.z, acc[i][3] + bv0.w};
        float4 o1 = {acc[i][4] + bv1.x, acc[i][5] + bv1.y,
                     acc[i][6] + bv1.z, acc[i][7] + bv1.w};
        *(float4*)(g_q + (size_t)row * N + bn + tx * 8) = o0;
        *(float4*)(g_q + (size_t)row * N + bn + tx * 8 + 4) = o1;
    }
}

// ---------------------------------------------------------------------------
// K2: z[m,r] = -(0.5/D) * ( sum_d q*(q*invw2 + b2) + cc[r] )   (dual-B NT)
// ---------------------------------------------------------------------------
__global__ __launch_bounds__(NT, 2) void k2_logits() {
    __shared__ float As[2][BK][BMP];
    __shared__ float B1s[2][BK][BMP];
    __shared__ float B2s[2][BK][BMP];
    const int K = DD, N = RR;
    int t = threadIdx.x;
    int bm = blockIdx.x * BM;
    int bn = blockIdx.y * BN;
    int tx = t & 15, ty = t >> 4;
    int lr = t >> 1;
    int lk = (t & 1) * 4;
    const float* Ap = g_q + (size_t)(bm + lr) * K + lk;
    const float* B1p = g_invw2 + (size_t)(bn + lr) * K + lk;
    const float* B2p = g_b2 + (size_t)(bn + lr) * K + lk;
    float acc[8][8] = {};
    {
        float4 va = *(const float4*)Ap;
        float4 v1 = *(const float4*)B1p;
        float4 v2 = *(const float4*)B2p;
        ST4(As[0], lk, lr, va);
        ST4(B1s[0], lk, lr, v1);
        ST4(B2s[0], lk, lr, v2);
    }
    __syncthreads();
    const int nk = K / BK;
    float4 pa, p1, p2;
    for (int kt = 0; kt < nk; kt++) {
        int buf = kt & 1;
        if (kt + 1 < nk) {
            pa = *(const float4*)(Ap + (kt + 1) * BK);
            p1 = *(const float4*)(B1p + (kt + 1) * BK);
            p2 = *(const float4*)(B2p + (kt + 1) * BK);
        }
#pragma unroll
        for (int k = 0; k < BK; k++) {
            float4 a0 = *(const float4*)&As[buf][k][ty * 8];
            float4 a1 = *(const float4*)&As[buf][k][ty * 8 + 4];
            float4 c0 = *(const float4*)&B1s[buf][k][tx * 8];
            float4 c1 = *(const float4*)&B1s[buf][k][tx * 8 + 4];
            float4 d0 = *(const float4*)&B2s[buf][k][tx * 8];
            float4 d1 = *(const float4*)&B2s[buf][k][tx * 8 + 4];
            float a[8] = {a0.x, a0.y, a0.z, a0.w, a1.x, a1.y, a1.z, a1.w};
            float b1[8] = {c0.x, c0.y, c0.z, c0.w, c1.x, c1.y, c1.z, c1.w};
            float b2[8] = {d0.x, d0.y, d0.z, d0.w, d1.x, d1.y, d1.z, d1.w};
#pragma unroll
            for (int i = 0; i < 8; i++)
#pragma unroll
                for (int j = 0; j < 8; j++) {
                    float tt = fmaf(a[i], b1[j], b2[j]);
                    acc[i][j] = fmaf(a[i], tt, acc[i][j]);
                }
        }
        if (kt + 1 < nk) {
            ST4(As[buf ^ 1], lk, lr, pa);
            ST4(B1s[buf ^ 1], lk, lr, p1);
            ST4(B2s[buf ^ 1], lk, lr, p2);
        }
        __syncthreads();
    }
    const float scale = -0.5f / (float)DD;
    float4 cc0 = *(const float4*)(g_cc + bn + tx * 8);
    float4 cc1 = *(const float4*)(g_cc + bn + tx * 8 + 4);
#pragma unroll
    for (int i = 0; i < 8; i++) {
        int row = bm + ty * 8 + i;
        float4 o0 = {scale * (acc[i][0] + cc0.x), scale * (acc[i][1] + cc0.y),
                     scale * (acc[i][2] + cc0.z), scale * (acc[i][3] + cc0.w)};
        float4 o1 = {scale * (acc[i][4] + cc1.x), scale * (acc[i][5] + cc1.y),
                     scale * (acc[i][6] + cc1.z), scale * (acc[i][7] + cc1.w)};
        *(float4*)(g_z + (size_t)row * N + bn + tx * 8) = o0;
        *(float4*)(g_z + (size_t)row * N + bn + tx * 8 + 4) = o1;
    }
}

// ---------------------------------------------------------------------------
// K3: softmax over R (in place on g_z); logits already scaled
// ---------------------------------------------------------------------------
__global__ void softmax_kernel() {
    int row = blockIdx.x;
    int t = threadIdx.x;  // 256
    float* zrow = g_z + (size_t)row * RR;
    float v0 = zrow[t];
    float v1 = zrow[t + 256];
    float m = fmaxf(v0, v1);
#pragma unroll
    for (int o = 16; o > 0; o >>= 1) m = fmaxf(m, __shfl_xor_sync(0xffffffffu, m, o));
    __shared__ float sm[8];
    __shared__ float ss[8];
    int wid = t >> 5, lid = t & 31;
    if (lid == 0) sm[wid] = m;
    __syncthreads();
    float mm = sm[0];
#pragma unroll
    for (int i = 1; i < 8; i++) mm = fmaxf(mm, sm[i]);
    float e0 = __expf(v0 - mm), e1 = __expf(v1 - mm);
    float s = e0 + e1;
#pragma unroll
    for (int o = 16; o > 0; o >>= 1) s += __shfl_xor_sync(0xffffffffu, s, o);
    if (lid == 0) ss[wid] = s;
    __syncthreads();
    float tot = 0.f;
#pragma unroll
    for (int i = 0; i < 8; i++) tot += ss[i];
    float inv = 1.0f / tot;
    zrow[t] = e0 * inv;
    zrow[t + 256] = e1 * inv;
}

// ---------------------------------------------------------------------------
// K4: conq[b,r,d] = sum_l Wc[r,l]*query[b,l,d] + bc[r]  (NN: B (K,N) rowmaj)
// ---------------------------------------------------------------------------
__global__ __launch_bounds__(NT, 2) void k4_conq(const float* __restrict__ Wc,
                                                 const float* __restrict__ query,
                                                 const float* __restrict__ bc) {
    __shared__ float As[2][BK][BMP];
    __shared__ float Bs[2][BK][BMP];
    const int K = LL, N = DD;
    int b = blockIdx.z;
    const float* Bm = query + (size_t)b * LL * DD;
    float* C = g_conq + (size_t)b * RR * DD;
    int t = threadIdx.x;
    int bm = blockIdx.x * BM;
    int bn = blockIdx.y * BN;
    int tx = t & 15, ty = t >> 4;
    int lr = t >> 1;
    int lk = (t & 1) * 4;
    int kr = t >> 5;           // 0..7
    int n4 = (t & 31) * 4;     // 0..124
    const float* Ap = Wc + (size_t)(bm + lr) * K + lk;
    const float* Bp = Bm + (size_t)kr * N + bn + n4;
    float acc[8][8] = {};
    {
        float4 va = *(const float4*)Ap;
        float4 vb = *(const float4*)Bp;
        ST4(As[0], lk, lr, va);
        *(float4*)&Bs[0][kr][n4] = vb;
    }
    __syncthreads();
    const int nk = K / BK;
    float4 pa, pb;
    for (int kt = 0; kt < nk; kt++) {
        int buf = kt & 1;
        if (kt + 1 < nk) {
            pa = *(const float4*)(Ap + (kt + 1) * BK);
            pb = *(const float4*)(Bp + (size_t)(kt + 1) * BK * N);
        }
#pragma unroll
        for (int k = 0; k < BK; k++) {
            float4 a0 = *(const float4*)&As[buf][k][ty * 8];
            float4 a1 = *(const float4*)&As[buf][k][ty * 8 + 4];
            float4 b0 = *(const float4*)&Bs[buf][k][tx * 8];
            float4 b1 = *(const float4*)&Bs[buf][k][tx * 8 + 4];
            float a[8] = {a0.x, a0.y, a0.z, a0.w, a1.x, a1.y, a1.z, a1.w};
            float bb[8] = {b0.x, b0.y, b0.z, b0.w, b1.x, b1.y, b1.z, b1.w};
#pragma unroll
            for (int i = 0; i < 8; i++)
#pragma unroll
                for (int j = 0; j < 8; j++) acc[i][j] += a[i] * bb[j];
        }
        if (kt + 1 < nk) {
            ST4(As[buf ^ 1], lk, lr, pa);
            *(float4*)&Bs[buf ^ 1][kr][n4] = pb;
        }
        __syncthreads();
    }
#pragma unroll
    for (int i = 0; i < 8; i++) {
        int row = bm + ty * 8 + i;
        float bias = bc[row];
        float4 o0 = {acc[i][0] + bias, acc[i][1] + bias,
                     acc[i][2] + bias, acc[i][3] + bias};
        float4 o1 = {acc[i][4] + bias, acc[i][5] + bias,
                     acc[i][6] + bias, acc[i][7] + bias};
        *(float4*)(C + (size_t)row * N + bn + tx * 8) = o0;
        *(float4*)(C + (size_t)row * N + bn + tx * 8 + 4) = o1;
    }
}

// ---------------------------------------------------------------------------
// K5: out[b,l,d] = sum_r Fss[b,l,r] * conq[b,r,d]   (NN gemm per batch)
// ---------------------------------------------------------------------------
__global__ __launch_bounds__(NT, 2) void k5_apply(float* __restrict__ out) {
    __shared__ float As[2][BK][BMP];
    __shared__ float Bs[2][BK][BMP];
    const int K = RR, N = DD;
    int b = blockIdx.z;
    const float* A = g_z + (size_t)b * LL * RR;
    const float* Bm = g_conq + (size_t)b * RR * DD;
    float* C = out + (size_t)b * LL * DD;
    int t = threadIdx.x;
    int bm = blockIdx.x * BM;
    int bn = blockIdx.y * BN;
    int tx = t & 15, ty = t >> 4;
    int lr = t >> 1;
    int lk = (t & 1) * 4;
    int kr = t >> 5;
    int n4 = (t & 31) * 4;
    const float* Ap = A + (size_t)(bm + lr) * K + lk;
    const float* Bp = Bm + (size_t)kr * N + bn + n4;
    float acc[8][8] = {};
    {
        float4 va = *(const float4*)Ap;
        float4 vb = *(const float4*)Bp;
        ST4(As[0], lk, lr, va);
        *(float4*)&Bs[0][kr][n4] = vb;
    }
    __syncthreads();
    const int nk = K / BK;
    float4 pa, pb;
    for (int kt = 0; kt < nk; kt++) {
        int buf = kt & 1;
        if (kt + 1 < nk) {
            pa = *(const float4*)(Ap + (kt + 1) * BK);
            pb = *(const float4*)(Bp + (size_t)(kt + 1) * BK * N);
        }
#pragma unroll
        for (int k = 0; k < BK; k++) {
            float4 a0 = *(const float4*)&As[buf][k][ty * 8];
            float4 a1 = *(const float4*)&As[buf][k][ty * 8 + 4];
            float4 b0 = *(const float4*)&Bs[buf][k][tx * 8];
            float4 b1 = *(const float4*)&Bs[buf][k][tx * 8 + 4];
            float a[8] = {a0.x, a0.y, a0.z, a0.w, a1.x, a1.y, a1.z, a1.w};
            float bb[8] = {b0.x, b0.y, b0.z, b0.w, b1.x, b1.y, b1.z, b1.w};
#pragma unroll
            for (int i = 0; i < 8; i++)
#pragma unroll
                for (int j = 0; j < 8; j++) acc[i][j] += a[i] * bb[j];
        }
        if (kt + 1 < nk) {
            ST4(As[buf ^ 1], lk, lr, pa);
            *(float4*)&Bs[buf ^ 1][kr][n4] = pb;
        }
        __syncthreads();
    }
#pragma unroll
    for (int i = 0; i < 8; i++) {
        int row = bm + ty * 8 + i;
        float4 o0 = {acc[i][0], acc[i][1], acc[i][2], acc[i][3]};
        float4 o1 = {acc[i][4], acc[i][5], acc[i][6], acc[i][7]};
        *(float4*)(C + (size_t)row * N + bn + tx * 8) = o0;
        *(float4*)(C + (size_t)row * N + bn + tx * 8 + 4) = o1;
    }
}

// ---------------------------------------------------------------------------
extern "C" void kernel_launch(void* const* d_in, const int* in_sizes, int n_in,
                              void* d_out, int out_size) {
    const float* query   = (const float*)d_in[0];   // (B,L,D)
    const float* Wq      = (const float*)d_in[1];   // (D,D)
    const float* bq      = (const float*)d_in[2];   // (D,)
    const float* Wc      = (const float*)d_in[3];   // (R,L)
    const float* bc      = (const float*)d_in[4];   // (R,)
    const float* centers = (const float*)d_in[5];   // (R,D)
    const float* widths  = (const float*)d_in[6];   // (R,D)
    float* out = (float*)d_out;                     // (B,L,D)

    prep_kernel<<<RR, 128>>>(centers, widths);

    dim3 g1(M1 / BM, DD / BN);
    k1_qproj<<<g1, NT>>>(query, Wq, bq);

    dim3 g2(M1 / BM, RR / BN);
    k2_logits<<<g2, NT>>>();

    softmax_kernel<<<M1, 256>>>();

    dim3 g4(RR / BM, DD / BN, BB);
    k4_conq<<<g4, NT>>>(Wc, query, bc);

    dim3 g5(LL / BM, DD / BN, BB);
    k5_apply<<<g5, NT>>>(out);
}

// round 4
// speedup vs baseline: 3.2215x; 1.9375x over previous
#include <cuda_runtime.h>
#include <cuda_bf16.h>
#include <cstdint>

// Problem constants
#define BB 8
#define LL 2048
#define DD 512
#define RR 512
#define M1 (BB * LL)   // 16384 flattened (B,L)

typedef __nv_bfloat16 bf16;
typedef __nv_bfloat162 bf162;

__device__ __forceinline__ uint32_t smem_to_u32(const void* smem_ptr) {
    uint32_t addr;
    asm("{ .reg .u64 tmp; cvta.to.shared.u64 tmp, %1; cvt.u32.u64 %0, tmp; }"
        : "=r"(addr) : "l"(smem_ptr));
    return addr;
}

__device__ __forceinline__ void bf16split(float x, bf16& h, bf16& l) {
    h = __float2bfloat16(x);
    l = __float2bfloat16(x - __bfloat162float(h));
}

#define CPASYNC16(dst, src) \
    asm volatile("cp.async.cg.shared.global [%0], [%1], 16;" :: "r"(dst), "l"(src))
#define CPASYNC_COMMIT() asm volatile("cp.async.commit_group;" ::: "memory")

#define LDSM4(r0, r1, r2, r3, addr) \
    asm volatile("ldmatrix.sync.aligned.m8n8.x4.shared.b16 {%0,%1,%2,%3}, [%4];" \
                 : "=r"(r0), "=r"(r1), "=r"(r2), "=r"(r3) : "r"(addr))

#define MMA16816(c, a, b) \
    asm volatile("mma.sync.aligned.m16n8k16.row.col.f32.bf16.bf16.f32 " \
                 "{%0,%1,%2,%3}, {%4,%5,%6,%7}, {%8,%9}, {%0,%1,%2,%3};" \
                 : "+f"((c)[0]), "+f"((c)[1]), "+f"((c)[2]), "+f"((c)[3]) \
                 : "r"((a)[0]), "r"((a)[1]), "r"((a)[2]), "r"((a)[3]), \
                   "r"((b)[0]), "r"((b)[1]))

// ---------------- scratch (device globals; no allocation allowed) ----------
__device__ bf16  g_query_h[(size_t)M1 * DD];
__device__ bf16  g_query_l[(size_t)M1 * DD];
__device__ bf16  g_wq_h[DD * DD];
__device__ bf16  g_wq_l[DD * DD];
__device__ bf16  g_wc_h[RR * LL];
__device__ bf16  g_wc_l[RR * LL];
__device__ bf16  g_qT_h[(size_t)BB * DD * LL];
__device__ bf16  g_qT_l[(size_t)BB * DD * LL];
__device__ bf16  g_qcat_h[(size_t)M1 * 1024];   // [q^2 | q]
__device__ bf16  g_qcat_l[(size_t)M1 * 1024];
__device__ bf16  g_bcat_h[RR * 1024];           // [invw2 | -2c*invw2]
__device__ bf16  g_bcat_l[RR * 1024];
__device__ float g_z[(size_t)M1 * RR];
__device__ bf16  g_fss_h[(size_t)M1 * RR];
__device__ bf16  g_fss_l[(size_t)M1 * RR];
__device__ bf16  g_conqT_h[(size_t)BB * DD * RR];
__device__ bf16  g_conqT_l[(size_t)BB * DD * RR];
__device__ float g_cc[RR];

// ---------------------------------------------------------------------------
// split: fp32 -> (hi, lo) bf16
// ---------------------------------------------------------------------------
__global__ void split_kernel(const float* __restrict__ src, bf16* __restrict__ hi,
                             bf16* __restrict__ lo, int n4) {
    int i = blockIdx.x * blockDim.x + threadIdx.x;
    if (i >= n4) return;
    float4 v = ((const float4*)src)[i];
    bf16 h0, l0, h1, l1, h2, l2, h3, l3;
    bf16split(v.x, h0, l0); bf16split(v.y, h1, l1);
    bf16split(v.z, h2, l2); bf16split(v.w, h3, l3);
    bf162 hh0; hh0.x = h0; hh0.y = h1;
    bf162 hh1; hh1.x = h2; hh1.y = h3;
    bf162 ll0; ll0.x = l0; ll0.y = l1;
    bf162 ll1; ll1.x = l2; ll1.y = l3;
    ((bf162*)hi)[i * 2 + 0] = hh0;
    ((bf162*)hi)[i * 2 + 1] = hh1;
    ((bf162*)lo)[i * 2 + 0] = ll0;
    ((bf162*)lo)[i * 2 + 1] = ll1;
}

// ---------------------------------------------------------------------------
// prep: bcat = [invw2 | -2c*invw2] split, cc[r] = sum c^2*invw2
// ---------------------------------------------------------------------------
__global__ void prep_kernel(const float* __restrict__ centers,
                            const float* __restrict__ widths) {
    int r = blockIdx.x;
    int t = threadIdx.x;  // 128
    float acc = 0.f;
    for (int d = t; d < DD; d += 128) {
        float w = widths[r * DD + d];
        float c = centers[r * DD + d];
        float iw = 1.0f / (w * w);
        float b2 = -2.0f * c * iw;
        bf16 h, l;
        bf16split(iw, h, l);
        g_bcat_h[r * 1024 + d] = h;
        g_bcat_l[r * 1024 + d] = l;
        bf16split(b2, h, l);
        g_bcat_h[r * 1024 + 512 + d] = h;
        g_bcat_l[r * 1024 + 512 + d] = l;
        acc += c * c * iw;
    }
    __shared__ float sred[128];
    sred[t] = acc;
    __syncthreads();
    for (int s = 64; s > 0; s >>= 1) {
        if (t < s) sred[t] += sred[t + s];
        __syncthreads();
    }
    if (t == 0) g_cc[r] = sred[0];
}

// ---------------------------------------------------------------------------
// transpose+split: qT[b,d,l] = query[b,l,d]
// ---------------------------------------------------------------------------
__global__ void transpose_split_kernel(const float* __restrict__ query) {
    __shared__ float tile[32][33];
    int b = blockIdx.z;
    int l0 = blockIdx.x * 32, d0 = blockIdx.y * 32;
    int tx = threadIdx.x, ty = threadIdx.y;
    const float* src = query + (size_t)b * LL * DD;
#pragma unroll
    for (int i = 0; i < 4; i++)
        tile[ty + 8 * i][tx] = src[(size_t)(l0 + ty + 8 * i) * DD + d0 + tx];
    __syncthreads();
    size_t base = (size_t)b * DD * LL;
#pragma unroll
    for (int i = 0; i < 4; i++) {
        float v = tile[tx][ty + 8 * i];
        bf16 h, l;
        bf16split(v, h, l);
        size_t idx = base + (size_t)(d0 + ty + 8 * i) * LL + l0 + tx;
        g_qT_h[idx] = h;
        g_qT_l[idx] = l;
    }
}

// ---------------------------------------------------------------------------
// bf16-split NT GEMM via mma.sync.m16n8k16 (3 passes: AhBh + AhBl + AlBh).
// A: (M,K) K-major split, B: (N,K) K-major split, both hi/lo.
// CTA: 128x128 tile, 256 thr, 8 warps of 64x32. K-chunk 32, cp.async 2-stage.
// SMEM tile: 128 rows x 64B data padded to 80B pitch (ldmatrix conflict-free).
// MODE 0: qcat epilogue  (write (v+aux)^2 | (v+aux) split; ldc=1024)
// MODE 1: fp32, scale*(v+aux[n]) -> Cf
// MODE 2: split bf16, v+aux[n]   -> Ch/Cl
// MODE 3: fp32 raw               -> Cf
// ---------------------------------------------------------------------------
#define TPITCH 80
#define TILE_B (128 * TPITCH)        // 10240
#define BUF_B  (4 * TILE_B)          // Ah, Al, Bh, Bl
#define GEMM_SMEM (2 * BUF_B)        // 81920

template <int MODE>
__global__ __launch_bounds__(256, 1) void gemm_bf16s(
    const bf16* __restrict__ Ah, const bf16* __restrict__ Al, int lda, size_t sA,
    const bf16* __restrict__ Bh, const bf16* __restrict__ Bl, int ldb, size_t sB,
    float* __restrict__ Cf, bf16* __restrict__ Ch, bf16* __restrict__ Cl,
    int ldc, size_t sC, const float* __restrict__ aux, int K) {
    extern __shared__ char smem[];
    uint32_t sb = smem_to_u32(smem);
    int t = threadIdx.x;
    int lane = t & 31, wid = t >> 5;
    int wm = wid & 1, wn = wid >> 1;
    int bn = blockIdx.x * 128, bm = blockIdx.y * 128;
    size_t bz = blockIdx.z;
    Ah += bz * sA; Al += bz * sA;
    Bh += bz * sB; Bl += bz * sB;

    // per-thread cp.async plan: 8 transfers of 16B per chunk
    const bf16* gp[8];
    uint32_t so[8];
#pragma unroll
    for (int tl = 0; tl < 4; tl++) {
#pragma unroll
        for (int i = 0; i < 2; i++) {
            int idx = t + i * 256;           // 0..511
            int row = idx >> 2;              // 0..127
            int c = idx & 3;                 // 16B column
            const bf16* src;
            if (tl == 0)      src = Ah + (size_t)(bm + row) * lda;
            else if (tl == 1) src = Al + (size_t)(bm + row) * lda;
            else if (tl == 2) src = Bh + (size_t)(bn + row) * ldb;
            else              src = Bl + (size_t)(bn + row) * ldb;
            gp[tl * 2 + i] = src + c * 8;
            so[tl * 2 + i] = tl * TILE_B + row * TPITCH + c * 16;
        }
    }

    float acc[4][4][4] = {};
    const int nk = K >> 5;

    // prologue: chunk 0 -> buf 0
#pragma unroll
    for (int u = 0; u < 8; u++) CPASYNC16(sb + so[u], gp[u]);
    CPASYNC_COMMIT();

    int lm = lane & 15, lq = lane >> 4;
    uint32_t a_off = (uint32_t)(wm * 64 + lm) * TPITCH + lq * 16;
    uint32_t b_off = (uint32_t)(wn * 32 + lm) * TPITCH + lq * 16;

    for (int kt = 0; kt < nk; kt++) {
        int buf = kt & 1;
        if (kt + 1 < nk) {
            uint32_t db = sb + (buf ^ 1) * BUF_B;
            int koff = (kt + 1) * 32;
#pragma unroll
            for (int u = 0; u < 8; u++) CPASYNC16(db + so[u], gp[u] + koff);
            CPASYNC_COMMIT();
            asm volatile("cp.async.wait_group 1;" ::: "memory");
        } else {
            asm volatile("cp.async.wait_group 0;" ::: "memory");
        }
        __syncthreads();
        uint32_t base = sb + buf * BUF_B;
#pragma unroll
        for (int ks = 0; ks < 2; ks++) {
            uint32_t kb = ks * 32;
            uint32_t a[4][4], bh[4][2], bl[4][2];
            // A hi fragments
#pragma unroll
            for (int i = 0; i < 4; i++)
                LDSM4(a[i][0], a[i][1], a[i][2], a[i][3],
                      base + a_off + i * (16 * TPITCH) + kb);
            // B hi fragments
#pragma unroll
            for (int jj = 0; jj < 2; jj++) {
                uint32_t r0, r1, r2, r3;
                LDSM4(r0, r1, r2, r3,
                      base + 2 * TILE_B + b_off + jj * (16 * TPITCH) + kb);
                bh[2 * jj][0] = r0; bh[2 * jj][1] = r2;
                bh[2 * jj + 1][0] = r1; bh[2 * jj + 1][1] = r3;
            }
#pragma unroll
            for (int i = 0; i < 4; i++)
#pragma unroll
                for (int j = 0; j < 4; j++) MMA16816(acc[i][j], a[i], bh[j]);
            // B lo fragments
#pragma unroll
            for (int jj = 0; jj < 2; jj++) {
                uint32_t r0, r1, r2, r3;
                LDSM4(r0, r1, r2, r3,
                      base + 3 * TILE_B + b_off + jj * (16 * TPITCH) + kb);
                bl[2 * jj][0] = r0; bl[2 * jj][1] = r2;
                bl[2 * jj + 1][0] = r1; bl[2 * jj + 1][1] = r3;
            }
#pragma unroll
            for (int i = 0; i < 4; i++)
#pragma unroll
                for (int j = 0; j < 4; j++) MMA16816(acc[i][j], a[i], bl[j]);
            // A lo fragments (overwrite a)
#pragma unroll
            for (int i = 0; i < 4; i++)
                LDSM4(a[i][0], a[i][1], a[i][2], a[i][3],
                      base + TILE_B + a_off + i * (16 * TPITCH) + kb);
#pragma unroll
            for (int i = 0; i < 4; i++)
#pragma unroll
                for (int j = 0; j < 4; j++) MMA16816(acc[i][j], a[i], bh[j]);
        }
        __syncthreads();
    }

    // epilogue
    int rbase = bm + wm * 64 + (lane >> 2);
    int nbase = bn + wn * 32 + (lane & 3) * 2;
#pragma unroll
    for (int i = 0; i < 4; i++) {
#pragma unroll
        for (int j = 0; j < 4; j++) {
            int n = nbase + j * 8;
#pragma unroll
            for (int h = 0; h < 2; h++) {
                int m = rbase + i * 16 + h * 8;
                float v0 = acc[i][j][2 * h];
                float v1 = acc[i][j][2 * h + 1];
                if (MODE == 0) {
                    size_t crow = (size_t)m * ldc;
                    float q0 = v0 + aux[n], q1 = v1 + aux[n + 1];
                    bf16 h0, l0, h1, l1;
                    bf16split(q0 * q0, h0, l0); bf16split(q1 * q1, h1, l1);
                    bf162 hh; hh.x = h0; hh.y = h1;
                    bf162 ll; ll.x = l0; ll.y = l1;
                    *(bf162*)(Ch + crow + n) = hh;
                    *(bf162*)(Cl + crow + n) = ll;
                    bf16split(q0, h0, l0); bf16split(q1, h1, l1);
                    hh.x = h0; hh.y = h1; ll.x = l0; ll.y = l1;
                    *(bf162*)(Ch + crow + 512 + n) = hh;
                    *(bf162*)(Cl + crow + 512 + n) = ll;
                } else if (MODE == 1) {
                    const float scale = -0.5f / (float)DD;
                    size_t crow = (size_t)m * ldc;
                    float2 o;
                    o.x = scale * (v0 + aux[n]);
                    o.y = scale * (v1 + aux[n + 1]);
                    *(float2*)(Cf + crow + n) = o;
                } else if (MODE == 2) {
                    size_t crow = bz * sC + (size_t)m * ldc;
                    float q0 = v0 + aux[n], q1 = v1 + aux[n + 1];
                    bf16 h0, l0, h1, l1;
                    bf16split(q0, h0, l0); bf16split(q1, h1, l1);
                    bf162 hh; hh.x = h0; hh.y = h1;
                    bf162 ll; ll.x = l0; ll.y = l1;
                    *(bf162*)(Ch + crow + n) = hh;
                    *(bf162*)(Cl + crow + n) = ll;
                } else {
                    size_t crow = bz * sC + (size_t)m * ldc;
                    float2 o; o.x = v0; o.y = v1;
                    *(float2*)(Cf + crow + n) = o;
                }
            }
        }
    }
}

// ---------------------------------------------------------------------------
// softmax over R: reads fp32 g_z (scaled logits), writes split Fss
// ---------------------------------------------------------------------------
__global__ void softmax_kernel() {
    int row = blockIdx.x;
    int t = threadIdx.x;  // 256
    const float* zrow = g_z + (size_t)row * RR;
    float v0 = zrow[t];
    float v1 = zrow[t + 256];
    float m = fmaxf(v0, v1);
#pragma unroll
    for (int o = 16; o > 0; o >>= 1) m = fmaxf(m, __shfl_xor_sync(0xffffffffu, m, o));
    __shared__ float sm[8];
    __shared__ float ss[8];
    int wid = t >> 5, lid = t & 31;
    if (lid == 0) sm[wid] = m;
    __syncthreads();
    float mm = sm[0];
#pragma unroll
    for (int i = 1; i < 8; i++) mm = fmaxf(mm, sm[i]);
    float e0 = __expf(v0 - mm), e1 = __expf(v1 - mm);
    float s = e0 + e1;
#pragma unroll
    for (int o = 16; o > 0; o >>= 1) s += __shfl_xor_sync(0xffffffffu, s, o);
    if (lid == 0) ss[wid] = s;
    __syncthreads();
    float tot = 0.f;
#pragma unroll
    for (int i = 0; i < 8; i++) tot += ss[i];
    float inv = 1.0f / tot;
    size_t i0 = (size_t)row * RR + t;
    size_t i1 = i0 + 256;
    bf16 h, l;
    bf16split(e0 * inv, h, l);
    g_fss_h[i0] = h; g_fss_l[i0] = l;
    bf16split(e1 * inv, h, l);
    g_fss_h[i1] = h; g_fss_l[i1] = l;
}

// ---------------------------------------------------------------------------
extern "C" void kernel_launch(void* const* d_in, const int* in_sizes, int n_in,
                              void* d_out, int out_size) {
    const float* query   = (const float*)d_in[0];   // (B,L,D)
    const float* Wq      = (const float*)d_in[1];   // (D,D)
    const float* bq      = (const float*)d_in[2];   // (D,)
    const float* Wc      = (const float*)d_in[3];   // (R,L)
    const float* bc      = (const float*)d_in[4];   // (R,)
    const float* centers = (const float*)d_in[5];   // (R,D)
    const float* widths  = (const float*)d_in[6];   // (R,D)
    float* out = (float*)d_out;                     // (B,L,D)

    cudaFuncSetAttribute(gemm_bf16s<0>, cudaFuncAttributeMaxDynamicSharedMemorySize, GEMM_SMEM);
    cudaFuncSetAttribute(gemm_bf16s<1>, cudaFuncAttributeMaxDynamicSharedMemorySize, GEMM_SMEM);
    cudaFuncSetAttribute(gemm_bf16s<2>, cudaFuncAttributeMaxDynamicSharedMemorySize, GEMM_SMEM);
    cudaFuncSetAttribute(gemm_bf16s<3>, cudaFuncAttributeMaxDynamicSharedMemorySize, GEMM_SMEM);

    bf16 *qh, *ql, *wqh, *wql, *wch, *wcl, *qTh, *qTl, *qch, *qcl;
    bf16 *bch_, *bcl_, *fh, *fl, *cth, *ctl;
    float *zp, *ccp;
    cudaGetSymbolAddress((void**)&qh, g_query_h);
    cudaGetSymbolAddress((void**)&ql, g_query_l);
    cudaGetSymbolAddress((void**)&wqh, g_wq_h);
    cudaGetSymbolAddress((void**)&wql, g_wq_l);
    cudaGetSymbolAddress((void**)&wch, g_wc_h);
    cudaGetSymbolAddress((void**)&wcl, g_wc_l);
    cudaGetSymbolAddress((void**)&qTh, g_qT_h);
    cudaGetSymbolAddress((void**)&qTl, g_qT_l);
    cudaGetSymbolAddress((void**)&qch, g_qcat_h);
    cudaGetSymbolAddress((void**)&qcl, g_qcat_l);
    cudaGetSymbolAddress((void**)&bch_, g_bcat_h);
    cudaGetSymbolAddress((void**)&bcl_, g_bcat_l);
    cudaGetSymbolAddress((void**)&fh, g_fss_h);
    cudaGetSymbolAddress((void**)&fl, g_fss_l);
    cudaGetSymbolAddress((void**)&cth, g_conqT_h);
    cudaGetSymbolAddress((void**)&ctl, g_conqT_l);
    cudaGetSymbolAddress((void**)&zp, g_z);
    cudaGetSymbolAddress((void**)&ccp, g_cc);

    // input splits
    {
        int n4 = (M1 * DD) / 4;
        split_kernel<<<(n4 + 255) / 256, 256>>>(query, qh, ql, n4);
        n4 = (DD * DD) / 4;
        split_kernel<<<(n4 + 255) / 256, 256>>>(Wq, wqh, wql, n4);
        n4 = (RR * LL) / 4;
        split_kernel<<<(n4 + 255) / 256, 256>>>(Wc, wch, wcl, n4);
    }
    prep_kernel<<<RR, 128>>>(centers, widths);
    {
        dim3 g(LL / 32, DD / 32, BB);
        dim3 b(32, 8);
        transpose_split_kernel<<<g, b>>>(query);
    }

    // G1: q = query @ Wq^T + bq -> qcat = [q^2 | q] split   (M=M1,N=D,K=D)
    {
        dim3 g(DD / 128, M1 / 128, 1);
        gemm_bf16s<0><<<g, 256, GEMM_SMEM>>>(qh, ql, DD, 0, wqh, wql, DD, 0,
                                             nullptr, qch, qcl, 1024, 0, bq, DD);
    }
    // G2: z = scale * (qcat @ bcat^T + cc)   (M=M1,N=R,K=1024)
    {
        dim3 g(RR / 128, M1 / 128, 1);
        gemm_bf16s<1><<<g, 256, GEMM_SMEM>>>(qch, qcl, 1024, 0, bch_, bcl_, 1024, 0,
                                             zp, nullptr, nullptr, RR, 0, ccp, 1024);
    }
    softmax_kernel<<<M1, 256>>>();
    // G4: conqT[b] = qT[b] @ Wc^T + bc   (M=D, N=R, K=L, batched)
    {
        dim3 g(RR / 128, DD / 128, BB);
        gemm_bf16s<2><<<g, 256, GEMM_SMEM>>>(qTh, qTl, LL, (size_t)DD * LL,
                                             wch, wcl, LL, 0,
                                             nullptr, cth, ctl, RR, (size_t)DD * RR, bc, LL);
    }
    // G5: out[b] = Fss[b] @ conqT[b]^T   (M=L, N=D, K=R, batched)
    {
        dim3 g(DD / 128, LL / 128, BB);
        gemm_bf16s<3><<<g, 256, GEMM_SMEM>>>(fh, fl, RR, (size_t)LL * RR,
                                             cth, ctl, RR, (size_t)DD * RR,
                                             out, nullptr, nullptr, DD, (size_t)LL * DD,
                                             nullptr, RR);
    }
}